// round 11
// baseline (speedup 1.0000x reference)
#include <cuda_runtime.h>
#include <cuda_fp16.h>
#include <cstdint>
#include <math.h>

// Problem constants
#define BSZ 32
#define LSEQ 4096
#define DIM 256
#define GDIM 768   // 3*DIM

// ---------------- scratch (device globals; no allocation allowed) ----------
__device__ float g_hs [BSZ * (LSEQ/2) * DIM];
__device__ float g_h1 [BSZ * (LSEQ/2) * DIM];
__device__ __half g_GI [(size_t)BSZ * LSEQ * GDIM];        // fp16 gate matrices
__device__ __half g_GH [(size_t)BSZ * (LSEQ/2) * GDIM];

// fp16 operand buffers
__device__ __half g_lh  [(size_t)BSZ * LSEQ * DIM];      // leaf fp16
__device__ __half g_eh  [(size_t)BSZ * (LSEQ/2) * DIM];  // emb fp16
__device__ __half g_h0h [(size_t)BSZ * (LSEQ/2) * DIM];
__device__ __half g_h1h [(size_t)BSZ * (LSEQ/2) * DIM];
__device__ __half g_wihh[GDIM * DIM];
__device__ __half g_whhh[GDIM * DIM];

// ======================= helpers ==========================
__device__ __forceinline__ uint32_t smem_u32(const void* p) {
    uint32_t a;
    asm("{ .reg .u64 t; cvta.to.shared.u64 t, %1; cvt.u32.u64 %0, t; }"
        : "=r"(a) : "l"(p));
    return a;
}

__device__ __forceinline__ uint32_t swz(uint32_t b) { return b ^ ((b >> 3) & 0x70); }

__device__ __forceinline__ void cp16(uint32_t dst, const void* src, int sz) {
    asm volatile("cp.async.cg.shared.global [%0], [%1], 16, %2;"
                 :: "r"(dst), "l"(src), "r"(sz));
}

#define CP_COMMIT() asm volatile("cp.async.commit_group;" ::: "memory")
#define CP_WAIT0()  asm volatile("cp.async.wait_group 0;" ::: "memory")

#define LDSM4(R, addr) \
    asm volatile("ldmatrix.sync.aligned.m8n8.x4.shared.b16 {%0,%1,%2,%3}, [%4];" \
        : "=r"((R)[0]), "=r"((R)[1]), "=r"((R)[2]), "=r"((R)[3]) : "r"(addr))

#define MMA_F16(C, A, B0, B1) \
    asm volatile("mma.sync.aligned.m16n8k16.row.col.f32.f16.f16.f32 " \
        "{%0,%1,%2,%3},{%4,%5,%6,%7},{%8,%9},{%0,%1,%2,%3};" \
        : "+f"((C)[0]), "+f"((C)[1]), "+f"((C)[2]), "+f"((C)[3]) \
        : "r"((A)[0]), "r"((A)[1]), "r"((A)[2]), "r"((A)[3]), "r"(B0), "r"(B1))

__device__ __forceinline__ void h4_store(float4 v, __half* __restrict__ dst, size_t idx) {
    __half2 lo = __floats2half2_rn(v.x, v.y);
    __half2 hi = __floats2half2_rn(v.z, v.w);
    *(uint2*)(dst + idx) = make_uint2(*(uint32_t*)&lo, *(uint32_t*)&hi);
}

// ======================= tensor-core GEMM (A-stationary fp16) ===============
// C[M,768] (fp16) = A[M,256] @ W[768,256]^T.
// CTA: 128 threads, M-tile 128, full K of A resident in smem; loops n_tiles
// N-tiles of 64, streaming 4KB W chunks through a 2-buffer ring. 3 CTAs/SM.
#define TBM 128
#define TBK 32
#define A_OPB 8192               // one A k-chunk: 128 rows * 64 B
#define W_OPB 4096               // one W chunk:    64 rows * 64 B
#define SM_A 0
#define SM_W (8*A_OPB)           // 64 KB
#define SMEM_GEMM (8*A_OPB + 2*W_OPB)   // 72 KB

__global__ void __launch_bounds__(128, 3) gemm_f16(
    const __half* __restrict__ A, const __half* __restrict__ W,
    __half* __restrict__ C, int M, int n_tiles)
{
    extern __shared__ char sm[];
    const uint32_t sb = smem_u32(sm);
    const int tid = threadIdx.x;
    const int wid = tid >> 5, lid = tid & 31;
    const int warpM = wid;
    const int bm  = blockIdx.x * TBM;
    const int bn0 = blockIdx.y * n_tiles * 64;

    const int arow = bm + tid;
    const int asz  = (arow < M) ? 16 : 0;
    const int arc  = (arow < M) ? arow : (M - 1);
    const char* Ap = (const char*)(A + (size_t)arc * DIM);
    const uint32_t wd0 = swz((uint32_t)(tid >> 1) * 64 + (tid & 1) * 32);
    const uint32_t wd1 = swz((uint32_t)(tid >> 1) * 64 + (tid & 1) * 32 + 16);

    auto loadW = [&](int c) {   // c = global chunk index: n = c/8, kc = c%8
        const char* Wp = (const char*)(W + (size_t)(bn0 + (c >> 3) * 64 + (tid >> 1)) * DIM);
        uint32_t base = sb + SM_W + (c & 1) * W_OPB;
        const int wgo = (c & 7) * 64 + (tid & 1) * 32;
        cp16(base + wd0, Wp + wgo,      16);
        cp16(base + wd1, Wp + wgo + 16, 16);
    };

    // prologue: all 8 A chunks + W chunk 0 in one group
    #pragma unroll
    for (int kc = 0; kc < 8; kc++) {
        #pragma unroll
        for (int j = 0; j < 4; j++) {
            uint32_t ad = swz((uint32_t)tid * 64 + j * 16);
            cp16(sb + SM_A + kc * A_OPB + ad, Ap + kc * 64 + j * 16, asz);
        }
    }
    loadW(0);
    CP_COMMIT();

    const int q  = lid >> 3;
    const int lq = lid & 7;
    const int total = n_tiles * 8;
    int c = 0;

    #pragma unroll 1
    for (int nt = 0; nt < n_tiles; nt++) {
        float acc[2][8][4];
        #pragma unroll
        for (int a = 0; a < 2; a++)
            #pragma unroll
            for (int b = 0; b < 8; b++)
                #pragma unroll
                for (int d = 0; d < 4; d++) acc[a][b][d] = 0.f;

        #pragma unroll 1
        for (int kc8 = 0; kc8 < 8; kc8++, c++) {
            CP_WAIT0();
            __syncthreads();
            if (c + 1 < total) { loadW(c + 1); CP_COMMIT(); }

            const uint32_t wbase = sb + SM_W + (c & 1) * W_OPB;
            const uint32_t abase = sb + SM_A + (c & 7) * A_OPB;

            #pragma unroll
            for (int ks = 0; ks < 2; ks++) {
                uint32_t bf[4][4];
                #pragma unroll
                for (int np = 0; np < 4; np++) {
                    int r  = np * 16 + ((q >> 1) << 3) + lq;
                    int kb = ks * 32 + ((q & 1) << 4);
                    LDSM4(bf[np], wbase + swz((uint32_t)r * 64 + kb));
                }
                uint32_t af[2][4];
                #pragma unroll
                for (int mt = 0; mt < 2; mt++) {
                    int r  = warpM * 32 + mt * 16 + ((q & 1) << 3) + lq;
                    int kb = ks * 32 + ((q >> 1) << 4);
                    LDSM4(af[mt], abase + swz((uint32_t)r * 64 + kb));
                }
                #pragma unroll
                for (int np = 0; np < 4; np++) {
                    #pragma unroll
                    for (int mt = 0; mt < 2; mt++) {
                        #pragma unroll
                        for (int h = 0; h < 2; h++) {
                            MMA_F16(acc[mt][np*2+h], af[mt], bf[np][h*2], bf[np][h*2+1]);
                        }
                    }
                }
            }
        }

        // epilogue: fp16 stores
        const int bn = bn0 + nt * 64;
        #pragma unroll
        for (int mt = 0; mt < 2; mt++) {
            int r0 = bm + warpM * 32 + mt * 16 + (lid >> 2);
            #pragma unroll
            for (int ntc = 0; ntc < 8; ntc++) {
                int col = bn + ntc * 8 + (lid & 3) * 2;
                if (r0 < M)
                    *(__half2*)(C + (size_t)r0 * GDIM + col) =
                        __floats2half2_rn(acc[mt][ntc][0], acc[mt][ntc][1]);
                if (r0 + 8 < M)
                    *(__half2*)(C + (size_t)(r0 + 8) * GDIM + col) =
                        __floats2half2_rn(acc[mt][ntc][2], acc[mt][ntc][3]);
            }
        }
    }
}

// ---------------- elementwise kernels --------------------------------------
__global__ void cvt_k(const float* __restrict__ x, __half* __restrict__ h, int n4)
{
    int i = blockIdx.x * blockDim.x + threadIdx.x;
    if (i >= n4) return;
    float4 v = ((const float4*)x)[i];
    h4_store(v, h, (size_t)i * 4);
}

// h0h (fp16 GEMM operand) = 0.5*(hs even + hs odd); no fp32 h0 materialized
__global__ void avg_k(const float* __restrict__ hs, __half* __restrict__ h0h, int m)
{
    int i = blockIdx.x * blockDim.x + threadIdx.x;
    int total = BSZ * m * (DIM / 4);
    if (i >= total) return;
    int dv = i & 63;
    int p  = i >> 6;
    int b = p / m, j = p - b * m;
    const float4* s0 = (const float4*)hs + ((size_t)(b * 2 * m + 2 * j)) * 64 + dv;
    float4 x = s0[0];
    float4 y = s0[64];
    float4 r = make_float4(0.5f*(x.x+y.x), 0.5f*(x.y+y.y),
                           0.5f*(x.z+y.z), 0.5f*(x.w+y.w));
    h4_store(r, h0h, (size_t)i * 4);
}

__device__ __forceinline__ float sigmf(float x) { return 1.f / (1.f + __expf(-x)); }

// h1 = GRU(xL, h0); h0 recomputed in fp32 from hs. GH null at level 0.
__global__ void gates1_k(const __half* __restrict__ GI, const __half* __restrict__ GH,
                         const float* __restrict__ hs,
                         const float* __restrict__ b_ih, const float* __restrict__ b_hh,
                         float* __restrict__ h1, __half* __restrict__ h1h, int m)
{
    int i = blockIdx.x * blockDim.x + threadIdx.x;
    int total = BSZ * m * DIM;
    if (i >= total) return;
    int d = i & 255;
    int p = i >> 8;
    int b = p / m, j = p - b * m;

    size_t gio = ((size_t)(b * 2 * m + 2 * j)) * GDIM;
    float gr = __half2float(GI[gio + d])       + b_ih[d];
    float gz = __half2float(GI[gio + 256 + d]) + b_ih[256 + d];
    float gn = __half2float(GI[gio + 512 + d]) + b_ih[512 + d];

    float hr = b_hh[d], hz = b_hh[256 + d], hn = b_hh[512 + d];
    float h0v = 0.f;
    if (GH) {
        size_t gho = (size_t)p * GDIM;
        hr += __half2float(GH[gho + d]);
        hz += __half2float(GH[gho + 256 + d]);
        hn += __half2float(GH[gho + 512 + d]);
        size_t hsrow = ((size_t)(b * 2 * m + 2 * j)) * DIM + d;
        h0v = 0.5f * (hs[hsrow] + hs[hsrow + DIM]);
    }
    float r  = sigmf(gr + hr);
    float z  = sigmf(gz + hz);
    float nn = tanhf(gn + r * hn);
    float v = (1.f - z) * nn + z * h0v;
    h1[i] = v;
    h1h[i] = __float2half(v);
}

__global__ void gates2_k(const __half* __restrict__ GI, const __half* __restrict__ GH,
                         const float* __restrict__ h1,
                         const float* __restrict__ b_ih, const float* __restrict__ b_hh,
                         float* __restrict__ emb_out,   // nullptr except final level
                         float* __restrict__ hs_out,
                         __half* __restrict__ eh, int m)
{
    int i = blockIdx.x * blockDim.x + threadIdx.x;
    int total = BSZ * m * DIM;
    if (i >= total) return;
    int d = i & 255;
    int p = i >> 8;
    int b = p / m, j = p - b * m;

    size_t gio = ((size_t)(b * 2 * m + 2 * j + 1)) * GDIM;
    float gr = __half2float(GI[gio + d])       + b_ih[d];
    float gz = __half2float(GI[gio + 256 + d]) + b_ih[256 + d];
    float gn = __half2float(GI[gio + 512 + d]) + b_ih[512 + d];

    size_t gho = (size_t)p * GDIM;
    float hr = __half2float(GH[gho + d])       + b_hh[d];
    float hz = __half2float(GH[gho + 256 + d]) + b_hh[256 + d];
    float hn = __half2float(GH[gho + 512 + d]) + b_hh[512 + d];

    float h1v = h1[i];
    float r  = sigmf(gr + hr);
    float z  = sigmf(gz + hz);
    float nn = tanhf(gn + r * hn);
    float h2 = (1.f - z) * nn + z * h1v;
    hs_out[i]  = h2;
    float ev = 0.5f * (h1v + h2);
    if (emb_out) emb_out[i] = ev;
    eh[i] = __float2half(ev);
}

// ---------------- host orchestration ---------------------------------------
static inline int pick_ntiles(int M) {
    int mb = (M + TBM - 1) / TBM;
    if (mb >= 444) return 6;   // 2 N-groups
    if (mb >= 222) return 3;   // 4 N-groups
    if (mb >= 148) return 2;   // 6 N-groups
    return 1;                  // 12 N-groups
}

extern "C" void kernel_launch(void* const* d_in, const int* in_sizes, int n_in,
                              void* d_out, int out_size)
{
    const float* leaf = (const float*)d_in[0];
    const float* W_ih = (const float*)d_in[1];
    const float* W_hh = (const float*)d_in[2];
    const float* b_ih = (const float*)d_in[3];
    const float* b_hh = (const float*)d_in[4];
    float* out = (float*)d_out;

    float *p_hs, *p_h1;
    __half *p_GI, *p_GH;
    __half *p_lh, *p_eh, *p_h0h, *p_h1h, *p_wihh, *p_whhh;
    { void* p; cudaGetSymbolAddress(&p, g_hs);   p_hs   = (float*)p; }
    { void* p; cudaGetSymbolAddress(&p, g_h1);   p_h1   = (float*)p; }
    { void* p; cudaGetSymbolAddress(&p, g_GI);   p_GI   = (__half*)p; }
    { void* p; cudaGetSymbolAddress(&p, g_GH);   p_GH   = (__half*)p; }
    { void* p; cudaGetSymbolAddress(&p, g_lh);   p_lh   = (__half*)p; }
    { void* p; cudaGetSymbolAddress(&p, g_eh);   p_eh   = (__half*)p; }
    { void* p; cudaGetSymbolAddress(&p, g_h0h);  p_h0h  = (__half*)p; }
    { void* p; cudaGetSymbolAddress(&p, g_h1h);  p_h1h  = (__half*)p; }
    { void* p; cudaGetSymbolAddress(&p, g_wihh); p_wihh = (__half*)p; }
    { void* p; cudaGetSymbolAddress(&p, g_whhh); p_whhh = (__half*)p; }

    cudaFuncSetAttribute(gemm_f16, cudaFuncAttributeMaxDynamicSharedMemorySize,
                         SMEM_GEMM);

    // convert weights + leaf to fp16
    {
        int n4 = GDIM * DIM / 4;
        cvt_k<<<(n4 + 255) / 256, 256>>>(W_ih, p_wihh, n4);
        cvt_k<<<(n4 + 255) / 256, 256>>>(W_hh, p_whhh, n4);
        int l4 = BSZ * LSEQ * DIM / 4;
        cvt_k<<<(l4 + 255) / 256, 256>>>(leaf, p_lh, l4);
    }

    int n = LSEQ;
    bool have_hs = false;

    while (n > 1) {
        const int m   = n / 2;
        const int Mgi = BSZ * n;
        const int Mh  = BSZ * m;
        const int tot  = Mh * DIM;
        const int tot4 = tot / 4;

        const __half* ah = have_hs ? p_eh : p_lh;

        {   // GI = embeds @ W_ih^T
            int nt = pick_ntiles(Mgi);
            dim3 grid((Mgi + TBM - 1) / TBM, 12 / nt);
            gemm_f16<<<grid, 128, SMEM_GEMM>>>(ah, p_wihh, p_GI, Mgi, nt);
        }

        if (have_hs) {
            avg_k<<<(tot4 + 255) / 256, 256>>>(p_hs, p_h0h, m);
            int nt = pick_ntiles(Mh);
            dim3 grid((Mh + TBM - 1) / TBM, 12 / nt);
            gemm_f16<<<grid, 128, SMEM_GEMM>>>(p_h0h, p_whhh, p_GH, Mh, nt);
        }

        gates1_k<<<(tot + 255) / 256, 256>>>(
            p_GI, have_hs ? p_GH : nullptr, p_hs,
            b_ih, b_hh, p_h1, p_h1h, m);

        {
            int nt = pick_ntiles(Mh);
            dim3 grid((Mh + TBM - 1) / TBM, 12 / nt);
            gemm_f16<<<grid, 128, SMEM_GEMM>>>(p_h1h, p_whhh, p_GH, Mh, nt);
        }

        gates2_k<<<(tot + 255) / 256, 256>>>(
            p_GI, p_GH, p_h1, b_ih, b_hh,
            (m == 1) ? out : nullptr, p_hs, p_eh, m);

        have_hs = true;
        n = m;
    }
}

// round 12
// speedup vs baseline: 1.5980x; 1.5980x over previous
#include <cuda_runtime.h>
#include <cuda_fp16.h>
#include <cstdint>
#include <math.h>

// Problem constants
#define BSZ 32
#define LSEQ 4096
#define DIM 256
#define GDIM 768   // 3*DIM

// ---------------- scratch (device globals; no allocation allowed) ----------
__device__ float  g_h1 [BSZ * (LSEQ/2) * DIM];             // 67 MB
__device__ float  g_h0f[BSZ * (LSEQ/4) * DIM];             // 33 MB (pair-avg fp32)
__device__ __half g_GI [(size_t)BSZ * LSEQ * GDIM];        // fp16 gate matrices
__device__ __half g_GH [(size_t)BSZ * (LSEQ/2) * GDIM];

// fp16 operand buffers
__device__ __half g_lh  [(size_t)BSZ * LSEQ * DIM];        // leaf fp16
__device__ __half g_eh  [(size_t)BSZ * (LSEQ/2) * DIM];    // emb fp16
__device__ __half g_h0h [(size_t)BSZ * (LSEQ/4) * DIM];    // pair-avg fp16
__device__ __half g_h1h [(size_t)BSZ * (LSEQ/2) * DIM];
__device__ __half g_wihh[GDIM * DIM];
__device__ __half g_whhh[GDIM * DIM];

// ======================= helpers ==========================
__device__ __forceinline__ uint32_t smem_u32(const void* p) {
    uint32_t a;
    asm("{ .reg .u64 t; cvta.to.shared.u64 t, %1; cvt.u32.u64 %0, t; }"
        : "=r"(a) : "l"(p));
    return a;
}

__device__ __forceinline__ uint32_t swz(uint32_t b) { return b ^ ((b >> 3) & 0x70); }

__device__ __forceinline__ void cp16(uint32_t dst, const void* src, int sz) {
    asm volatile("cp.async.cg.shared.global [%0], [%1], 16, %2;"
                 :: "r"(dst), "l"(src), "r"(sz));
}

#define CP_COMMIT() asm volatile("cp.async.commit_group;" ::: "memory")
#define CP_WAIT0()  asm volatile("cp.async.wait_group 0;" ::: "memory")

#define LDSM4(R, addr) \
    asm volatile("ldmatrix.sync.aligned.m8n8.x4.shared.b16 {%0,%1,%2,%3}, [%4];" \
        : "=r"((R)[0]), "=r"((R)[1]), "=r"((R)[2]), "=r"((R)[3]) : "r"(addr))

#define MMA_F16(C, A, B0, B1) \
    asm volatile("mma.sync.aligned.m16n8k16.row.col.f32.f16.f16.f32 " \
        "{%0,%1,%2,%3},{%4,%5,%6,%7},{%8,%9},{%0,%1,%2,%3};" \
        : "+f"((C)[0]), "+f"((C)[1]), "+f"((C)[2]), "+f"((C)[3]) \
        : "r"((A)[0]), "r"((A)[1]), "r"((A)[2]), "r"((A)[3]), "r"(B0), "r"(B1))

__device__ __forceinline__ void h4_store(float4 v, __half* __restrict__ dst, size_t idx) {
    __half2 lo = __floats2half2_rn(v.x, v.y);
    __half2 hi = __floats2half2_rn(v.z, v.w);
    *(uint2*)(dst + idx) = make_uint2(*(uint32_t*)&lo, *(uint32_t*)&hi);
}

// load 4 consecutive fp16 -> float4
__device__ __forceinline__ float4 h4_load(const __half* __restrict__ src, size_t idx) {
    uint2 raw = *(const uint2*)(src + idx);
    __half2 a = *(__half2*)&raw.x;
    __half2 b = *(__half2*)&raw.y;
    float2 fa = __half22float2(a);
    float2 fb = __half22float2(b);
    return make_float4(fa.x, fa.y, fb.x, fb.y);
}

// ======================= tensor-core GEMM (A-stationary fp16) ===============
// C[M,768] (fp16) = A[M,256] @ W[768,256]^T.
#define TBM 128
#define TBK 32
#define A_OPB 8192               // one A k-chunk: 128 rows * 64 B
#define W_OPB 4096               // one W chunk:    64 rows * 64 B
#define SM_A 0
#define SM_W (8*A_OPB)           // 64 KB
#define SMEM_GEMM (8*A_OPB + 2*W_OPB)   // 72 KB

__global__ void __launch_bounds__(128, 3) gemm_f16(
    const __half* __restrict__ A, const __half* __restrict__ W,
    __half* __restrict__ C, int M, int n_tiles)
{
    extern __shared__ char sm[];
    const uint32_t sb = smem_u32(sm);
    const int tid = threadIdx.x;
    const int wid = tid >> 5, lid = tid & 31;
    const int warpM = wid;
    const int bm  = blockIdx.x * TBM;
    const int bn0 = blockIdx.y * n_tiles * 64;

    const int arow = bm + tid;
    const int asz  = (arow < M) ? 16 : 0;
    const int arc  = (arow < M) ? arow : (M - 1);
    const char* Ap = (const char*)(A + (size_t)arc * DIM);
    const uint32_t wd0 = swz((uint32_t)(tid >> 1) * 64 + (tid & 1) * 32);
    const uint32_t wd1 = swz((uint32_t)(tid >> 1) * 64 + (tid & 1) * 32 + 16);

    auto loadW = [&](int c) {   // c = global chunk index: n = c/8, kc = c%8
        const char* Wp = (const char*)(W + (size_t)(bn0 + (c >> 3) * 64 + (tid >> 1)) * DIM);
        uint32_t base = sb + SM_W + (c & 1) * W_OPB;
        const int wgo = (c & 7) * 64 + (tid & 1) * 32;
        cp16(base + wd0, Wp + wgo,      16);
        cp16(base + wd1, Wp + wgo + 16, 16);
    };

    // prologue: all 8 A chunks + W chunk 0 in one group
    #pragma unroll
    for (int kc = 0; kc < 8; kc++) {
        #pragma unroll
        for (int j = 0; j < 4; j++) {
            uint32_t ad = swz((uint32_t)tid * 64 + j * 16);
            cp16(sb + SM_A + kc * A_OPB + ad, Ap + kc * 64 + j * 16, asz);
        }
    }
    loadW(0);
    CP_COMMIT();

    const int q  = lid >> 3;
    const int lq = lid & 7;
    const int total = n_tiles * 8;
    int c = 0;

    #pragma unroll 1
    for (int nt = 0; nt < n_tiles; nt++) {
        float acc[2][8][4];
        #pragma unroll
        for (int a = 0; a < 2; a++)
            #pragma unroll
            for (int b = 0; b < 8; b++)
                #pragma unroll
                for (int d = 0; d < 4; d++) acc[a][b][d] = 0.f;

        #pragma unroll 1
        for (int kc8 = 0; kc8 < 8; kc8++, c++) {
            CP_WAIT0();
            __syncthreads();
            if (c + 1 < total) { loadW(c + 1); CP_COMMIT(); }

            const uint32_t wbase = sb + SM_W + (c & 1) * W_OPB;
            const uint32_t abase = sb + SM_A + (c & 7) * A_OPB;

            #pragma unroll
            for (int ks = 0; ks < 2; ks++) {
                uint32_t bf[4][4];
                #pragma unroll
                for (int np = 0; np < 4; np++) {
                    int r  = np * 16 + ((q >> 1) << 3) + lq;
                    int kb = ks * 32 + ((q & 1) << 4);
                    LDSM4(bf[np], wbase + swz((uint32_t)r * 64 + kb));
                }
                uint32_t af[2][4];
                #pragma unroll
                for (int mt = 0; mt < 2; mt++) {
                    int r  = warpM * 32 + mt * 16 + ((q & 1) << 3) + lq;
                    int kb = ks * 32 + ((q >> 1) << 4);
                    LDSM4(af[mt], abase + swz((uint32_t)r * 64 + kb));
                }
                #pragma unroll
                for (int np = 0; np < 4; np++) {
                    #pragma unroll
                    for (int mt = 0; mt < 2; mt++) {
                        #pragma unroll
                        for (int h = 0; h < 2; h++) {
                            MMA_F16(acc[mt][np*2+h], af[mt], bf[np][h*2], bf[np][h*2+1]);
                        }
                    }
                }
            }
        }

        // epilogue: fp16 stores
        const int bn = bn0 + nt * 64;
        #pragma unroll
        for (int mt = 0; mt < 2; mt++) {
            int r0 = bm + warpM * 32 + mt * 16 + (lid >> 2);
            #pragma unroll
            for (int ntc = 0; ntc < 8; ntc++) {
                int col = bn + ntc * 8 + (lid & 3) * 2;
                if (r0 < M)
                    *(__half2*)(C + (size_t)r0 * GDIM + col) =
                        __floats2half2_rn(acc[mt][ntc][0], acc[mt][ntc][1]);
                if (r0 + 8 < M)
                    *(__half2*)(C + (size_t)(r0 + 8) * GDIM + col) =
                        __floats2half2_rn(acc[mt][ntc][2], acc[mt][ntc][3]);
            }
        }
    }
}

// ---------------- elementwise kernels --------------------------------------
__global__ void cvt_k(const float* __restrict__ x, __half* __restrict__ h, int n4)
{
    int i = blockIdx.x * blockDim.x + threadIdx.x;
    if (i >= n4) return;
    float4 v = ((const float4*)x)[i];
    h4_store(v, h, (size_t)i * 4);
}

__device__ __forceinline__ float sigmf(float x) { return 1.f / (1.f + __expf(-x)); }

// vec4 GRU gate core: given gate rows + h0, produce new h (4 lanes)
__device__ __forceinline__ float4 gru4(float4 gr, float4 gz, float4 gn,
                                       float4 hr, float4 hz, float4 hn,
                                       float4 h0)
{
    float4 o;
    {
        float r = sigmf(gr.x + hr.x), z = sigmf(gz.x + hz.x);
        float nn = tanhf(gn.x + r * hn.x);
        o.x = (1.f - z) * nn + z * h0.x;
    }
    {
        float r = sigmf(gr.y + hr.y), z = sigmf(gz.y + hz.y);
        float nn = tanhf(gn.y + r * hn.y);
        o.y = (1.f - z) * nn + z * h0.y;
    }
    {
        float r = sigmf(gr.z + hr.z), z = sigmf(gz.z + hz.z);
        float nn = tanhf(gn.z + r * hn.z);
        o.z = (1.f - z) * nn + z * h0.z;
    }
    {
        float r = sigmf(gr.w + hr.w), z = sigmf(gz.w + hz.w);
        float nn = tanhf(gn.w + r * hn.w);
        o.w = (1.f - z) * nn + z * h0.w;
    }
    return o;
}

__device__ __forceinline__ float4 f4add(float4 a, float4 b) {
    return make_float4(a.x + b.x, a.y + b.y, a.z + b.z, a.w + b.w);
}

// h1 = GRU(xL, h0); h0f precomputed by previous level's gates2 (null level 0).
// 4 dims/thread; exact grid (2048*m threads).
__global__ void gates1_k(const __half* __restrict__ GI, const __half* __restrict__ GH,
                         const float* __restrict__ h0f,
                         const float* __restrict__ b_ih, const float* __restrict__ b_hh,
                         float* __restrict__ h1, __half* __restrict__ h1h, int m)
{
    int i = blockIdx.x * blockDim.x + threadIdx.x;   // over BSZ*m*64
    int d4 = (i & 63) * 4;
    int p  = i >> 6;
    int b = p / m, j = p - b * m;

    size_t gio = ((size_t)(b * 2 * m + 2 * j)) * GDIM;
    float4 gr = f4add(h4_load(GI, gio + d4),       *(const float4*)(b_ih + d4));
    float4 gz = f4add(h4_load(GI, gio + 256 + d4), *(const float4*)(b_ih + 256 + d4));
    float4 gn = f4add(h4_load(GI, gio + 512 + d4), *(const float4*)(b_ih + 512 + d4));

    float4 hr = *(const float4*)(b_hh + d4);
    float4 hz = *(const float4*)(b_hh + 256 + d4);
    float4 hn = *(const float4*)(b_hh + 512 + d4);
    float4 h0 = make_float4(0.f, 0.f, 0.f, 0.f);
    if (GH) {
        size_t gho = (size_t)p * GDIM;
        hr = f4add(hr, h4_load(GH, gho + d4));
        hz = f4add(hz, h4_load(GH, gho + 256 + d4));
        hn = f4add(hn, h4_load(GH, gho + 512 + d4));
        h0 = *(const float4*)(h0f + (size_t)p * DIM + d4);
    }
    float4 v = gru4(gr, gz, gn, hr, hz, hn, h0);
    *(float4*)(h1 + (size_t)p * DIM + d4) = v;
    h4_store(v, h1h, (size_t)p * DIM + d4);
}

// h2 = GRU(xR, h1); paired blocks (2 sibling nodes) emit next level's
// h0f/h0h = 0.5*(h2L+h2R) and this level's emb fp16. m >= 2.
__global__ void gates2_k(const __half* __restrict__ GI, const __half* __restrict__ GH,
                         const float* __restrict__ h1,
                         const float* __restrict__ b_ih, const float* __restrict__ b_hh,
                         float* __restrict__ h0f, __half* __restrict__ h0h,
                         __half* __restrict__ eh, int m)
{
    __shared__ float4 sh[128];
    const int m2 = m >> 1;
    const int pp = blockIdx.x;            // pair index over BSZ*m2
    const int b = pp / m2, qq = pp - b * m2;
    const int tid = threadIdx.x;
    const int side = tid >> 6;            // 0 = left child, 1 = right child
    const int d4 = (tid & 63) * 4;
    const int j = 2 * qq + side;
    const int p = b * m + j;

    size_t gio = ((size_t)(b * 2 * m + 2 * j + 1)) * GDIM;
    float4 gr = f4add(h4_load(GI, gio + d4),       *(const float4*)(b_ih + d4));
    float4 gz = f4add(h4_load(GI, gio + 256 + d4), *(const float4*)(b_ih + 256 + d4));
    float4 gn = f4add(h4_load(GI, gio + 512 + d4), *(const float4*)(b_ih + 512 + d4));

    size_t gho = (size_t)p * GDIM;
    float4 hr = f4add(h4_load(GH, gho + d4),       *(const float4*)(b_hh + d4));
    float4 hz = f4add(h4_load(GH, gho + 256 + d4), *(const float4*)(b_hh + 256 + d4));
    float4 hn = f4add(h4_load(GH, gho + 512 + d4), *(const float4*)(b_hh + 512 + d4));

    float4 h1v = *(const float4*)(h1 + (size_t)p * DIM + d4);
    float4 h2 = gru4(gr, gz, gn, hr, hz, hn, h1v);

    // emb (this level's output nodes) in fp16 for next level's GI GEMM
    float4 ev = make_float4(0.5f * (h1v.x + h2.x), 0.5f * (h1v.y + h2.y),
                            0.5f * (h1v.z + h2.z), 0.5f * (h1v.w + h2.w));
    h4_store(ev, eh, (size_t)p * DIM + d4);

    sh[tid] = h2;
    __syncthreads();
    if (side == 0) {
        float4 o = sh[tid + 64];
        float4 av = make_float4(0.5f * (h2.x + o.x), 0.5f * (h2.y + o.y),
                                0.5f * (h2.z + o.z), 0.5f * (h2.w + o.w));
        size_t oi = (size_t)(b * m2 + qq) * DIM + d4;
        *(float4*)(h0f + oi) = av;
        h4_store(av, h0h, oi);
    }
}

// final level (m == 1): h2 = GRU(xR, h1); out = 0.5*(h1+h2). Exact 2048 threads.
__global__ void gates2_last(const __half* __restrict__ GI, const __half* __restrict__ GH,
                            const float* __restrict__ h1,
                            const float* __restrict__ b_ih, const float* __restrict__ b_hh,
                            float* __restrict__ out)
{
    int i = blockIdx.x * blockDim.x + threadIdx.x;   // over BSZ*64
    int d4 = (i & 63) * 4;
    int b  = i >> 6;

    size_t gio = ((size_t)(b * 2 + 1)) * GDIM;
    float4 gr = f4add(h4_load(GI, gio + d4),       *(const float4*)(b_ih + d4));
    float4 gz = f4add(h4_load(GI, gio + 256 + d4), *(const float4*)(b_ih + 256 + d4));
    float4 gn = f4add(h4_load(GI, gio + 512 + d4), *(const float4*)(b_ih + 512 + d4));

    size_t gho = (size_t)b * GDIM;
    float4 hr = f4add(h4_load(GH, gho + d4),       *(const float4*)(b_hh + d4));
    float4 hz = f4add(h4_load(GH, gho + 256 + d4), *(const float4*)(b_hh + 256 + d4));
    float4 hn = f4add(h4_load(GH, gho + 512 + d4), *(const float4*)(b_hh + 512 + d4));

    float4 h1v = *(const float4*)(h1 + (size_t)b * DIM + d4);
    float4 h2 = gru4(gr, gz, gn, hr, hz, hn, h1v);
    *(float4*)(out + (size_t)b * DIM + d4) =
        make_float4(0.5f * (h1v.x + h2.x), 0.5f * (h1v.y + h2.y),
                    0.5f * (h1v.z + h2.z), 0.5f * (h1v.w + h2.w));
}

// ---------------- host orchestration ---------------------------------------
static inline int pick_ntiles(int M) {
    int mb = (M + TBM - 1) / TBM;
    if (mb >= 444) return 6;   // 2 N-groups
    if (mb >= 222) return 3;   // 4 N-groups
    if (mb >= 148) return 2;   // 6 N-groups
    return 1;                  // 12 N-groups
}

extern "C" void kernel_launch(void* const* d_in, const int* in_sizes, int n_in,
                              void* d_out, int out_size)
{
    const float* leaf = (const float*)d_in[0];
    const float* W_ih = (const float*)d_in[1];
    const float* W_hh = (const float*)d_in[2];
    const float* b_ih = (const float*)d_in[3];
    const float* b_hh = (const float*)d_in[4];
    float* out = (float*)d_out;

    float *p_h1, *p_h0f;
    __half *p_GI, *p_GH, *p_lh, *p_eh, *p_h0h, *p_h1h, *p_wihh, *p_whhh;
    { void* p; cudaGetSymbolAddress(&p, g_h1);   p_h1   = (float*)p; }
    { void* p; cudaGetSymbolAddress(&p, g_h0f);  p_h0f  = (float*)p; }
    { void* p; cudaGetSymbolAddress(&p, g_GI);   p_GI   = (__half*)p; }
    { void* p; cudaGetSymbolAddress(&p, g_GH);   p_GH   = (__half*)p; }
    { void* p; cudaGetSymbolAddress(&p, g_lh);   p_lh   = (__half*)p; }
    { void* p; cudaGetSymbolAddress(&p, g_eh);   p_eh   = (__half*)p; }
    { void* p; cudaGetSymbolAddress(&p, g_h0h);  p_h0h  = (__half*)p; }
    { void* p; cudaGetSymbolAddress(&p, g_h1h);  p_h1h  = (__half*)p; }
    { void* p; cudaGetSymbolAddress(&p, g_wihh); p_wihh = (__half*)p; }
    { void* p; cudaGetSymbolAddress(&p, g_whhh); p_whhh = (__half*)p; }

    cudaFuncSetAttribute(gemm_f16, cudaFuncAttributeMaxDynamicSharedMemorySize,
                         SMEM_GEMM);

    // convert weights + leaf to fp16
    {
        int n4 = GDIM * DIM / 4;
        cvt_k<<<(n4 + 255) / 256, 256>>>(W_ih, p_wihh, n4);
        cvt_k<<<(n4 + 255) / 256, 256>>>(W_hh, p_whhh, n4);
        int l4 = BSZ * LSEQ * DIM / 4;
        cvt_k<<<(l4 + 255) / 256, 256>>>(leaf, p_lh, l4);
    }

    int n = LSEQ;
    bool have_hs = false;

    while (n > 1) {
        const int m   = n / 2;
        const int Mgi = BSZ * n;
        const int Mh  = BSZ * m;

        const __half* ah = have_hs ? p_eh : p_lh;

        {   // GI = embeds @ W_ih^T
            int nt = pick_ntiles(Mgi);
            dim3 grid((Mgi + TBM - 1) / TBM, 12 / nt);
            gemm_f16<<<grid, 128, SMEM_GEMM>>>(ah, p_wihh, p_GI, Mgi, nt);
        }

        if (have_hs) {   // GH0 = h0 @ W_hh^T (h0h from previous gates2)
            int nt = pick_ntiles(Mh);
            dim3 grid((Mh + TBM - 1) / TBM, 12 / nt);
            gemm_f16<<<grid, 128, SMEM_GEMM>>>(p_h0h, p_whhh, p_GH, Mh, nt);
        }

        gates1_k<<<(BSZ * m * 64) / 256 ? (BSZ * m * 64) / 256 : 1, 256>>>(
            p_GI, have_hs ? p_GH : nullptr, p_h0f,
            b_ih, b_hh, p_h1, p_h1h, m);

        {   // GH1 = h1 @ W_hh^T
            int nt = pick_ntiles(Mh);
            dim3 grid((Mh + TBM - 1) / TBM, 12 / nt);
            gemm_f16<<<grid, 128, SMEM_GEMM>>>(p_h1h, p_whhh, p_GH, Mh, nt);
        }

        if (m >= 2) {
            gates2_k<<<BSZ * (m / 2), 128>>>(
                p_GI, p_GH, p_h1, b_ih, b_hh, p_h0f, p_h0h, p_eh, m);
        } else {
            gates2_last<<<(BSZ * 64) / 128, 128>>>(
                p_GI, p_GH, p_h1, b_ih, b_hh, out);
        }

        have_hs = true;
        n = m;
    }
}

// round 13
// speedup vs baseline: 1.6826x; 1.0529x over previous
#include <cuda_runtime.h>
#include <cuda_fp16.h>
#include <cstdint>
#include <math.h>

// Problem constants
#define BSZ 32
#define LSEQ 4096
#define DIM 256
#define GDIM 768   // 3*DIM

// ---------------- scratch (device globals; no allocation allowed) ----------
__device__ float  g_h1 [BSZ * (LSEQ/2) * DIM];             // 67 MB
__device__ float  g_h0f[BSZ * (LSEQ/4) * DIM];             // 33 MB (pair-avg fp32)
__device__ __half g_GI [(size_t)BSZ * LSEQ * GDIM];        // fp16 gate matrices
__device__ __half g_GH [(size_t)BSZ * (LSEQ/2) * GDIM];

// fp16 operand buffers
__device__ __half g_lh  [(size_t)BSZ * LSEQ * DIM];        // leaf fp16
__device__ __half g_eh  [(size_t)BSZ * (LSEQ/2) * DIM];    // emb fp16
__device__ __half g_h0h [(size_t)BSZ * (LSEQ/4) * DIM];    // pair-avg fp16
__device__ __half g_h1h [(size_t)BSZ * (LSEQ/2) * DIM];
__device__ __half g_wihh[GDIM * DIM];
__device__ __half g_whhh[GDIM * DIM];

// ======================= helpers ==========================
__device__ __forceinline__ uint32_t smem_u32(const void* p) {
    uint32_t a;
    asm("{ .reg .u64 t; cvta.to.shared.u64 t, %1; cvt.u32.u64 %0, t; }"
        : "=r"(a) : "l"(p));
    return a;
}

__device__ __forceinline__ uint32_t swz(uint32_t b) { return b ^ ((b >> 3) & 0x70); }

__device__ __forceinline__ void cp16(uint32_t dst, const void* src, int sz) {
    asm volatile("cp.async.cg.shared.global [%0], [%1], 16, %2;"
                 :: "r"(dst), "l"(src), "r"(sz));
}

#define CP_COMMIT() asm volatile("cp.async.commit_group;" ::: "memory")
#define CP_WAIT0()  asm volatile("cp.async.wait_group 0;" ::: "memory")

#define LDSM4(R, addr) \
    asm volatile("ldmatrix.sync.aligned.m8n8.x4.shared.b16 {%0,%1,%2,%3}, [%4];" \
        : "=r"((R)[0]), "=r"((R)[1]), "=r"((R)[2]), "=r"((R)[3]) : "r"(addr))

#define MMA_F16(C, A, B0, B1) \
    asm volatile("mma.sync.aligned.m16n8k16.row.col.f32.f16.f16.f32 " \
        "{%0,%1,%2,%3},{%4,%5,%6,%7},{%8,%9},{%0,%1,%2,%3};" \
        : "+f"((C)[0]), "+f"((C)[1]), "+f"((C)[2]), "+f"((C)[3]) \
        : "r"((A)[0]), "r"((A)[1]), "r"((A)[2]), "r"((A)[3]), "r"(B0), "r"(B1))

__device__ __forceinline__ void h4_store(float4 v, __half* __restrict__ dst, size_t idx) {
    __half2 lo = __floats2half2_rn(v.x, v.y);
    __half2 hi = __floats2half2_rn(v.z, v.w);
    *(uint2*)(dst + idx) = make_uint2(*(uint32_t*)&lo, *(uint32_t*)&hi);
}

__device__ __forceinline__ float4 h4_load(const __half* __restrict__ src, size_t idx) {
    uint2 raw = *(const uint2*)(src + idx);
    __half2 a = *(__half2*)&raw.x;
    __half2 b = *(__half2*)&raw.y;
    float2 fa = __half22float2(a);
    float2 fb = __half22float2(b);
    return make_float4(fa.x, fa.y, fb.x, fb.y);
}

// ======================= tensor-core GEMM (A-stationary fp16, dual-mode) ====
// blockIdx.z selects operand set: z=0 -> (A,W,C,M); z=1 -> (A2,W2,C2,M2).
// Lets two independent GEMMs (GI and GH0) co-schedule in one launch, merging
// their wave tails. Blocks past their set's M range exit immediately.
#define TBM 128
#define TBK 32
#define A_OPB 8192               // one A k-chunk: 128 rows * 64 B
#define W_OPB 4096               // one W chunk:    64 rows * 64 B
#define SM_A 0
#define SM_W (8*A_OPB)           // 64 KB
#define SMEM_GEMM (8*A_OPB + 2*W_OPB)   // 72 KB

__global__ void __launch_bounds__(128, 3) gemm_f16(
    const __half* __restrict__ A,  const __half* __restrict__ W,
    __half* __restrict__ C,  int M,
    const __half* __restrict__ A2, const __half* __restrict__ W2,
    __half* __restrict__ C2, int M2,
    int n_tiles)
{
    extern __shared__ char sm[];
    const uint32_t sb = smem_u32(sm);
    const int tid = threadIdx.x;
    const int wid = tid >> 5, lid = tid & 31;
    const int warpM = wid;
    const int bm  = blockIdx.x * TBM;
    const int bn0 = blockIdx.y * n_tiles * 64;

    // select operand set by z
    const __half* Ag; const __half* Wg; __half* Cg; int Mg;
    if (blockIdx.z == 0) { Ag = A;  Wg = W;  Cg = C;  Mg = M;  }
    else                 { Ag = A2; Wg = W2; Cg = C2; Mg = M2; }
    if (bm >= Mg) return;

    const int arow = bm + tid;
    const int asz  = (arow < Mg) ? 16 : 0;
    const int arc  = (arow < Mg) ? arow : (Mg - 1);
    const char* Ap = (const char*)(Ag + (size_t)arc * DIM);
    const uint32_t wd0 = swz((uint32_t)(tid >> 1) * 64 + (tid & 1) * 32);
    const uint32_t wd1 = swz((uint32_t)(tid >> 1) * 64 + (tid & 1) * 32 + 16);

    auto loadW = [&](int c) {   // c = global chunk index: n = c/8, kc = c%8
        const char* Wp = (const char*)(Wg + (size_t)(bn0 + (c >> 3) * 64 + (tid >> 1)) * DIM);
        uint32_t base = sb + SM_W + (c & 1) * W_OPB;
        const int wgo = (c & 7) * 64 + (tid & 1) * 32;
        cp16(base + wd0, Wp + wgo,      16);
        cp16(base + wd1, Wp + wgo + 16, 16);
    };

    // prologue: all 8 A chunks + W chunk 0 in one group
    #pragma unroll
    for (int kc = 0; kc < 8; kc++) {
        #pragma unroll
        for (int j = 0; j < 4; j++) {
            uint32_t ad = swz((uint32_t)tid * 64 + j * 16);
            cp16(sb + SM_A + kc * A_OPB + ad, Ap + kc * 64 + j * 16, asz);
        }
    }
    loadW(0);
    CP_COMMIT();

    const int q  = lid >> 3;
    const int lq = lid & 7;
    const int total = n_tiles * 8;
    int c = 0;

    #pragma unroll 1
    for (int nt = 0; nt < n_tiles; nt++) {
        float acc[2][8][4];
        #pragma unroll
        for (int a = 0; a < 2; a++)
            #pragma unroll
            for (int b = 0; b < 8; b++)
                #pragma unroll
                for (int d = 0; d < 4; d++) acc[a][b][d] = 0.f;

        #pragma unroll 1
        for (int kc8 = 0; kc8 < 8; kc8++, c++) {
            CP_WAIT0();
            __syncthreads();
            if (c + 1 < total) { loadW(c + 1); CP_COMMIT(); }

            const uint32_t wbase = sb + SM_W + (c & 1) * W_OPB;
            const uint32_t abase = sb + SM_A + (c & 7) * A_OPB;

            #pragma unroll
            for (int ks = 0; ks < 2; ks++) {
                uint32_t bf[4][4];
                #pragma unroll
                for (int np = 0; np < 4; np++) {
                    int r  = np * 16 + ((q >> 1) << 3) + lq;
                    int kb = ks * 32 + ((q & 1) << 4);
                    LDSM4(bf[np], wbase + swz((uint32_t)r * 64 + kb));
                }
                uint32_t af[2][4];
                #pragma unroll
                for (int mt = 0; mt < 2; mt++) {
                    int r  = warpM * 32 + mt * 16 + ((q & 1) << 3) + lq;
                    int kb = ks * 32 + ((q >> 1) << 4);
                    LDSM4(af[mt], abase + swz((uint32_t)r * 64 + kb));
                }
                #pragma unroll
                for (int np = 0; np < 4; np++) {
                    #pragma unroll
                    for (int mt = 0; mt < 2; mt++) {
                        #pragma unroll
                        for (int h = 0; h < 2; h++) {
                            MMA_F16(acc[mt][np*2+h], af[mt], bf[np][h*2], bf[np][h*2+1]);
                        }
                    }
                }
            }
        }

        // epilogue: fp16 stores
        const int bn = bn0 + nt * 64;
        #pragma unroll
        for (int mt = 0; mt < 2; mt++) {
            int r0 = bm + warpM * 32 + mt * 16 + (lid >> 2);
            #pragma unroll
            for (int ntc = 0; ntc < 8; ntc++) {
                int col = bn + ntc * 8 + (lid & 3) * 2;
                if (r0 < Mg)
                    *(__half2*)(Cg + (size_t)r0 * GDIM + col) =
                        __floats2half2_rn(acc[mt][ntc][0], acc[mt][ntc][1]);
                if (r0 + 8 < Mg)
                    *(__half2*)(Cg + (size_t)(r0 + 8) * GDIM + col) =
                        __floats2half2_rn(acc[mt][ntc][2], acc[mt][ntc][3]);
            }
        }
    }
}

// ---------------- elementwise kernels --------------------------------------
__global__ void cvt_k(const float* __restrict__ x, __half* __restrict__ h, int n4)
{
    int i = blockIdx.x * blockDim.x + threadIdx.x;
    if (i >= n4) return;
    float4 v = ((const float4*)x)[i];
    h4_store(v, h, (size_t)i * 4);
}

__device__ __forceinline__ float sigmf(float x) { return 1.f / (1.f + __expf(-x)); }

__device__ __forceinline__ float4 gru4(float4 gr, float4 gz, float4 gn,
                                       float4 hr, float4 hz, float4 hn,
                                       float4 h0)
{
    float4 o;
    {
        float r = sigmf(gr.x + hr.x), z = sigmf(gz.x + hz.x);
        float nn = tanhf(gn.x + r * hn.x);
        o.x = (1.f - z) * nn + z * h0.x;
    }
    {
        float r = sigmf(gr.y + hr.y), z = sigmf(gz.y + hz.y);
        float nn = tanhf(gn.y + r * hn.y);
        o.y = (1.f - z) * nn + z * h0.y;
    }
    {
        float r = sigmf(gr.z + hr.z), z = sigmf(gz.z + hz.z);
        float nn = tanhf(gn.z + r * hn.z);
        o.z = (1.f - z) * nn + z * h0.z;
    }
    {
        float r = sigmf(gr.w + hr.w), z = sigmf(gz.w + hz.w);
        float nn = tanhf(gn.w + r * hn.w);
        o.w = (1.f - z) * nn + z * h0.w;
    }
    return o;
}

__device__ __forceinline__ float4 f4add(float4 a, float4 b) {
    return make_float4(a.x + b.x, a.y + b.y, a.z + b.z, a.w + b.w);
}

// h1 = GRU(xL, h0); h0f precomputed by previous level's gates2 (null level 0).
__global__ void gates1_k(const __half* __restrict__ GI, const __half* __restrict__ GH,
                         const float* __restrict__ h0f,
                         const float* __restrict__ b_ih, const float* __restrict__ b_hh,
                         float* __restrict__ h1, __half* __restrict__ h1h, int m)
{
    int i = blockIdx.x * blockDim.x + threadIdx.x;   // over BSZ*m*64
    int d4 = (i & 63) * 4;
    int p  = i >> 6;
    int b = p / m, j = p - b * m;

    size_t gio = ((size_t)(b * 2 * m + 2 * j)) * GDIM;
    float4 gr = f4add(h4_load(GI, gio + d4),       *(const float4*)(b_ih + d4));
    float4 gz = f4add(h4_load(GI, gio + 256 + d4), *(const float4*)(b_ih + 256 + d4));
    float4 gn = f4add(h4_load(GI, gio + 512 + d4), *(const float4*)(b_ih + 512 + d4));

    float4 hr = *(const float4*)(b_hh + d4);
    float4 hz = *(const float4*)(b_hh + 256 + d4);
    float4 hn = *(const float4*)(b_hh + 512 + d4);
    float4 h0 = make_float4(0.f, 0.f, 0.f, 0.f);
    if (GH) {
        size_t gho = (size_t)p * GDIM;
        hr = f4add(hr, h4_load(GH, gho + d4));
        hz = f4add(hz, h4_load(GH, gho + 256 + d4));
        hn = f4add(hn, h4_load(GH, gho + 512 + d4));
        h0 = *(const float4*)(h0f + (size_t)p * DIM + d4);
    }
    float4 v = gru4(gr, gz, gn, hr, hz, hn, h0);
    *(float4*)(h1 + (size_t)p * DIM + d4) = v;
    h4_store(v, h1h, (size_t)p * DIM + d4);
}

// h2 = GRU(xR, h1); paired blocks emit next level's h0f/h0h and emb fp16. m>=2.
__global__ void gates2_k(const __half* __restrict__ GI, const __half* __restrict__ GH,
                         const float* __restrict__ h1,
                         const float* __restrict__ b_ih, const float* __restrict__ b_hh,
                         float* __restrict__ h0f, __half* __restrict__ h0h,
                         __half* __restrict__ eh, int m)
{
    __shared__ float4 sh[128];
    const int m2 = m >> 1;
    const int pp = blockIdx.x;            // pair index over BSZ*m2
    const int b = pp / m2, qq = pp - b * m2;
    const int tid = threadIdx.x;
    const int side = tid >> 6;
    const int d4 = (tid & 63) * 4;
    const int j = 2 * qq + side;
    const int p = b * m + j;

    size_t gio = ((size_t)(b * 2 * m + 2 * j + 1)) * GDIM;
    float4 gr = f4add(h4_load(GI, gio + d4),       *(const float4*)(b_ih + d4));
    float4 gz = f4add(h4_load(GI, gio + 256 + d4), *(const float4*)(b_ih + 256 + d4));
    float4 gn = f4add(h4_load(GI, gio + 512 + d4), *(const float4*)(b_ih + 512 + d4));

    size_t gho = (size_t)p * GDIM;
    float4 hr = f4add(h4_load(GH, gho + d4),       *(const float4*)(b_hh + d4));
    float4 hz = f4add(h4_load(GH, gho + 256 + d4), *(const float4*)(b_hh + 256 + d4));
    float4 hn = f4add(h4_load(GH, gho + 512 + d4), *(const float4*)(b_hh + 512 + d4));

    float4 h1v = *(const float4*)(h1 + (size_t)p * DIM + d4);
    float4 h2 = gru4(gr, gz, gn, hr, hz, hn, h1v);

    float4 ev = make_float4(0.5f * (h1v.x + h2.x), 0.5f * (h1v.y + h2.y),
                            0.5f * (h1v.z + h2.z), 0.5f * (h1v.w + h2.w));
    h4_store(ev, eh, (size_t)p * DIM + d4);

    sh[tid] = h2;
    __syncthreads();
    if (side == 0) {
        float4 o = sh[tid + 64];
        float4 av = make_float4(0.5f * (h2.x + o.x), 0.5f * (h2.y + o.y),
                                0.5f * (h2.z + o.z), 0.5f * (h2.w + o.w));
        size_t oi = (size_t)(b * m2 + qq) * DIM + d4;
        *(float4*)(h0f + oi) = av;
        h4_store(av, h0h, oi);
    }
}

// final level (m == 1)
__global__ void gates2_last(const __half* __restrict__ GI, const __half* __restrict__ GH,
                            const float* __restrict__ h1,
                            const float* __restrict__ b_ih, const float* __restrict__ b_hh,
                            float* __restrict__ out)
{
    int i = blockIdx.x * blockDim.x + threadIdx.x;   // over BSZ*64
    int d4 = (i & 63) * 4;
    int b  = i >> 6;

    size_t gio = ((size_t)(b * 2 + 1)) * GDIM;
    float4 gr = f4add(h4_load(GI, gio + d4),       *(const float4*)(b_ih + d4));
    float4 gz = f4add(h4_load(GI, gio + 256 + d4), *(const float4*)(b_ih + 256 + d4));
    float4 gn = f4add(h4_load(GI, gio + 512 + d4), *(const float4*)(b_ih + 512 + d4));

    size_t gho = (size_t)b * GDIM;
    float4 hr = f4add(h4_load(GH, gho + d4),       *(const float4*)(b_hh + d4));
    float4 hz = f4add(h4_load(GH, gho + 256 + d4), *(const float4*)(b_hh + 256 + d4));
    float4 hn = f4add(h4_load(GH, gho + 512 + d4), *(const float4*)(b_hh + 512 + d4));

    float4 h1v = *(const float4*)(h1 + (size_t)b * DIM + d4);
    float4 h2 = gru4(gr, gz, gn, hr, hz, hn, h1v);
    *(float4*)(out + (size_t)b * DIM + d4) =
        make_float4(0.5f * (h1v.x + h2.x), 0.5f * (h1v.y + h2.y),
                    0.5f * (h1v.z + h2.z), 0.5f * (h1v.w + h2.w));
}

// ---------------- host orchestration ---------------------------------------
static inline int pick_ntiles(int M) {
    int mb = (M + TBM - 1) / TBM;
    if (mb >= 444) return 6;   // 2 N-groups
    if (mb >= 222) return 3;   // 4 N-groups
    if (mb >= 148) return 2;   // 6 N-groups
    return 1;                  // 12 N-groups
}

extern "C" void kernel_launch(void* const* d_in, const int* in_sizes, int n_in,
                              void* d_out, int out_size)
{
    const float* leaf = (const float*)d_in[0];
    const float* W_ih = (const float*)d_in[1];
    const float* W_hh = (const float*)d_in[2];
    const float* b_ih = (const float*)d_in[3];
    const float* b_hh = (const float*)d_in[4];
    float* out = (float*)d_out;

    float *p_h1, *p_h0f;
    __half *p_GI, *p_GH, *p_lh, *p_eh, *p_h0h, *p_h1h, *p_wihh, *p_whhh;
    { void* p; cudaGetSymbolAddress(&p, g_h1);   p_h1   = (float*)p; }
    { void* p; cudaGetSymbolAddress(&p, g_h0f);  p_h0f  = (float*)p; }
    { void* p; cudaGetSymbolAddress(&p, g_GI);   p_GI   = (__half*)p; }
    { void* p; cudaGetSymbolAddress(&p, g_GH);   p_GH   = (__half*)p; }
    { void* p; cudaGetSymbolAddress(&p, g_lh);   p_lh   = (__half*)p; }
    { void* p; cudaGetSymbolAddress(&p, g_eh);   p_eh   = (__half*)p; }
    { void* p; cudaGetSymbolAddress(&p, g_h0h);  p_h0h  = (__half*)p; }
    { void* p; cudaGetSymbolAddress(&p, g_h1h);  p_h1h  = (__half*)p; }
    { void* p; cudaGetSymbolAddress(&p, g_wihh); p_wihh = (__half*)p; }
    { void* p; cudaGetSymbolAddress(&p, g_whhh); p_whhh = (__half*)p; }

    cudaFuncSetAttribute(gemm_f16, cudaFuncAttributeMaxDynamicSharedMemorySize,
                         SMEM_GEMM);

    // convert weights + leaf to fp16
    {
        int n4 = GDIM * DIM / 4;
        cvt_k<<<(n4 + 255) / 256, 256>>>(W_ih, p_wihh, n4);
        cvt_k<<<(n4 + 255) / 256, 256>>>(W_hh, p_whhh, n4);
        int l4 = BSZ * LSEQ * DIM / 4;
        cvt_k<<<(l4 + 255) / 256, 256>>>(leaf, p_lh, l4);
    }

    int n = LSEQ;
    bool have_hs = false;

    while (n > 1) {
        const int m   = n / 2;
        const int Mgi = BSZ * n;
        const int Mh  = BSZ * m;

        const __half* ah = have_hs ? p_eh : p_lh;

        {   // fused: GI = embeds @ W_ih^T  ||  GH0 = h0 @ W_hh^T (z-dim)
            int nt = pick_ntiles(Mgi);
            int Mh_eff = have_hs ? Mh : 0;
            dim3 grid((Mgi + TBM - 1) / TBM, 12 / nt, have_hs ? 2 : 1);
            gemm_f16<<<grid, 128, SMEM_GEMM>>>(
                ah, p_wihh, p_GI, Mgi,
                p_h0h, p_whhh, p_GH, Mh_eff, nt);
        }

        gates1_k<<<(BSZ * m * 64) / 256 ? (BSZ * m * 64) / 256 : 1, 256>>>(
            p_GI, have_hs ? p_GH : nullptr, p_h0f,
            b_ih, b_hh, p_h1, p_h1h, m);

        {   // GH1 = h1 @ W_hh^T (single-set launch, z extent 1)
            int nt = pick_ntiles(Mh);
            dim3 grid((Mh + TBM - 1) / TBM, 12 / nt, 1);
            gemm_f16<<<grid, 128, SMEM_GEMM>>>(
                p_h1h, p_whhh, p_GH, Mh,
                p_h1h, p_whhh, p_GH, 0, nt);
        }

        if (m >= 2) {
            gates2_k<<<BSZ * (m / 2), 128>>>(
                p_GI, p_GH, p_h1, b_ih, b_hh, p_h0f, p_h0h, p_eh, m);
        } else {
            gates2_last<<<(BSZ * 64) / 128, 128>>>(
                p_GI, p_GH, p_h1, b_ih, b_hh, out);
        }

        have_hs = true;
        n = m;
    }
}